// round 4
// baseline (speedup 1.0000x reference)
#include <cuda_runtime.h>
#include <cstdint>

// Problem constants
#define BB 64      // batch
#define TT 512     // seq len
#define DD 256     // input dim
#define UU 512     // units
#define MM 64      // memory slots
#define NN 2112    // 4*U + M
#define KK 768     // D + U

#define NBLK 132   // 66 n-stripes x 2 batch-halves
#define BN 32      // n cols per stripe
#define MH 32      // batch rows per block

// dynamic smem layout (floats)
//  s_W : [768][32]      24576 f   (persistent weight stripe)
//  s_a : [128][33]       4224 f   (A chunk stage, padded)
//  s_p : [8][32][33]     8448 f   (cross-kg partials, padded)
#define SW_OFF 0
#define SA_OFF 24576
#define SP_OFF 28800
#define SMEM_FLOATS 37248
#define SMEM_BYTES (SMEM_FLOATS * 4)

// -------- device scratch (no allocations allowed) --------
__device__ float g_W[KK * NN];
__device__ float g_b[NN];
__device__ float g_h[BB * UU];
__device__ float g_z[BB * NN];
__device__ float g_mem[BB * MM * UU];
__device__ unsigned g_count = 0;
__device__ unsigned g_epoch = 0;

// =====================================================================
// Init: pack W/U/b into [768 x 2112], zero h and mem.
// =====================================================================
__global__ void init_kernel(
    const float* __restrict__ Wi, const float* __restrict__ Ui, const float* __restrict__ bi,
    const float* __restrict__ Wf, const float* __restrict__ Uf, const float* __restrict__ bf,
    const float* __restrict__ Wo, const float* __restrict__ Uo, const float* __restrict__ bo,
    const float* __restrict__ Wc, const float* __restrict__ Uc, const float* __restrict__ bc,
    const float* __restrict__ We, const float* __restrict__ Ue, const float* __restrict__ be)
{
    int stride = gridDim.x * blockDim.x;
    int t0 = blockIdx.x * blockDim.x + threadIdx.x;

    for (int i = t0; i < KK * NN; i += stride) {
        int k = i / NN;
        int n = i - k * NN;
        float v;
        if (n < 4 * UU) {
            int g = n >> 9;
            int col = n & (UU - 1);
            const float* s;
            if (k < DD) {
                s = (g == 0) ? Wi : (g == 1) ? Wf : (g == 2) ? Wo : Wc;
                v = s[k * UU + col];
            } else {
                s = (g == 0) ? Ui : (g == 1) ? Uf : (g == 2) ? Uo : Uc;
                v = s[(k - DD) * UU + col];
            }
        } else {
            int col = n - 4 * UU;
            v = (k < DD) ? We[k * MM + col] : Ue[(k - DD) * MM + col];
        }
        g_W[i] = v;
    }
    for (int i = t0; i < NN; i += stride) {
        float v;
        if (i < 4 * UU) {
            int g = i >> 9;
            int col = i & (UU - 1);
            v = (g == 0) ? bi[col] : (g == 1) ? bf[col] : (g == 2) ? bo[col] : bc[col];
        } else {
            v = be[i - 4 * UU];
        }
        g_b[i] = v;
    }
    for (int i = t0; i < BB * UU; i += stride) g_h[i] = 0.0f;
    for (int i = t0; i < BB * MM * UU; i += stride) g_mem[i] = 0.0f;
}

// =====================================================================
// Grid-wide software barrier (count + monotonic epoch).
// All NBLK blocks are co-resident (132 blocks <= 148 SMs, 1 block/SM).
// =====================================================================
__device__ __forceinline__ void grid_barrier(unsigned* my_epoch)
{
    __syncthreads();
    if (threadIdx.x == 0) {
        unsigned target = *my_epoch + 1u;
        __threadfence();                       // publish prior global writes
        unsigned v = atomicAdd(&g_count, 1u);
        if (v == NBLK - 1) {
            atomicExch(&g_count, 0u);
            __threadfence();
            atomicExch(&g_epoch, target);      // release
        } else {
            while ((int)(*((volatile unsigned*)&g_epoch) - target) < 0) { }
        }
        *my_epoch = target;
    }
    __syncthreads();
}

__device__ __forceinline__ void ffma2(unsigned long long& acc,
                                      unsigned long long a2,
                                      unsigned long long b2)
{
    asm("fma.rn.f32x2 %0, %1, %2, %0;" : "+l"(acc) : "l"(a2), "l"(b2));
}

// =====================================================================
// Persistent kernel: 512 x { GEMM -> barrier -> pointwise -> barrier }.
// Block = (n-stripe, batch-half): z[m0:m0+32, n0:n0+32] over K=768.
// 8 warps split K (96 each); lane = batch row; 32 n-cols per lane as
// 16 packed f32x2 accumulators. W stripe lives in smem for all steps.
// =====================================================================
__global__ __launch_bounds__(256, 1) void xlstm_persistent(
    const float* __restrict__ x, float* __restrict__ out)
{
    extern __shared__ float smem[];
    float* s_W = smem + SW_OFF;
    float* s_a = smem + SA_OFF;
    float* s_p = smem + SP_OFF;
    __shared__ float s_e[MM];
    __shared__ float s_ew[MM];

    const int tid    = threadIdx.x;
    const int lane   = tid & 31;
    const int warp   = tid >> 5;           // = kg (0..7)
    const int blk    = blockIdx.x;
    const int stripe = blk >> 1;
    const int bh     = blk & 1;
    const int n0     = stripe * BN;
    const int m0     = bh * MH;

    // ---- load W stripe into smem once (persistent across all 512 steps)
#pragma unroll 4
    for (int q = 0; q < 96; ++q) {
        int i = tid + q * 256;             // 0..24575
        int k = i >> 5, n = i & 31;
        s_W[i] = g_W[k * NN + n0 + n];
    }

    unsigned my_epoch = 0;
    if (tid == 0) my_epoch = *((volatile unsigned*)&g_epoch);
    __syncthreads();

    for (int t = 0; t < TT; ++t) {
        // ============================ GEMM ============================
        unsigned long long acc[16];
#pragma unroll
        for (int q = 0; q < 16; ++q) acc[q] = 0ull;

        float rA[16];
        // prologue: chunk 0 -> registers
#pragma unroll
        for (int q = 0; q < 16; ++q) {
            int i    = tid + q * 256;
            int mr   = i >> 7;             // 0..31
            int slot = i & 127;
            int k    = (slot >> 4) * 96 + (slot & 15);
            int gm   = m0 + mr;
            rA[q] = (k < DD) ? x[gm * (TT * DD) + t * DD + k]
                             : __ldcg(&g_h[gm * UU + (k - DD)]);
        }

#pragma unroll 1
        for (int c = 0; c < 6; ++c) {
            __syncthreads();
#pragma unroll
            for (int q = 0; q < 16; ++q) {
                int i    = tid + q * 256;
                int mr   = i >> 7;
                int slot = i & 127;
                s_a[slot * 33 + mr] = rA[q];
            }
            __syncthreads();

            if (c < 5) {                   // prefetch next chunk
#pragma unroll
                for (int q = 0; q < 16; ++q) {
                    int i    = tid + q * 256;
                    int mr   = i >> 7;
                    int slot = i & 127;
                    int k    = (slot >> 4) * 96 + (c + 1) * 16 + (slot & 15);
                    int gm   = m0 + mr;
                    rA[q] = (k < DD) ? x[gm * (TT * DD) + t * DD + k]
                                     : __ldcg(&g_h[gm * UU + (k - DD)]);
                }
            }

            const float* ap = s_a + (warp * 16) * 33 + lane;
            const ulonglong2* bp =
                (const ulonglong2*)(s_W + (warp * 96 + c * 16) * 32);
#pragma unroll
            for (int j = 0; j < 16; ++j) {
                float a = ap[j * 33];
                unsigned long long a2;
                asm("mov.b64 %0, {%1, %1};" : "=l"(a2) : "f"(a));
#pragma unroll
                for (int p = 0; p < 8; ++p) {
                    ulonglong2 bv = bp[j * 8 + p];
                    ffma2(acc[2 * p],     a2, bv.x);
                    ffma2(acc[2 * p + 1], a2, bv.y);
                }
            }
        }

        // cross-kg reduction (deterministic, via smem)
        __syncthreads();
        {
            float* pr = s_p + (warp * 32 + lane) * 33;
#pragma unroll
            for (int q = 0; q < 16; ++q) {
                float2 f = *(float2*)&acc[q];
                pr[2 * q]     = f.x;
                pr[2 * q + 1] = f.y;
            }
        }
        __syncthreads();
#pragma unroll
        for (int q = 0; q < 4; ++q) {
            int i  = tid + q * 256;        // 0..1023
            int mr = i >> 5;
            int n  = i & 31;
            float sum = g_b[n0 + n];
#pragma unroll
            for (int kg = 0; kg < 8; ++kg)
                sum += s_p[(kg * 32 + mr) * 33 + n];
            g_z[(m0 + mr) * NN + n0 + n] = sum;
        }

        grid_barrier(&my_epoch);

        // ========================== pointwise =========================
        if (blk < 2 * BB) {
            const int b    = blk >> 1;
            const int half = blk & 1;

            if (tid < 32) {
                float z0 = __ldcg(&g_z[b * NN + 4 * UU + tid]);
                float z1 = __ldcg(&g_z[b * NN + 4 * UU + 32 + tid]);
                float mx = fmaxf(z0, z1);
#pragma unroll
                for (int o = 16; o > 0; o >>= 1)
                    mx = fmaxf(mx, __shfl_xor_sync(0xffffffffu, mx, o));
                float e0 = __expf(z0 - mx);
                float e1 = __expf(z1 - mx);
                float sm = e0 + e1;
#pragma unroll
                for (int o = 16; o > 0; o >>= 1)
                    sm += __shfl_xor_sync(0xffffffffu, sm, o);
                float inv = 1.0f / sm;
                s_e[tid]      = e0 * inv;
                s_e[tid + 32] = e1 * inv;
            }
            __syncthreads();
            // physical slot s holds c_{t'} with memory-index m = (t-1-s) & 63
            if (tid < MM) s_ew[tid] = s_e[(t - 1 - tid) & (MM - 1)];
            __syncthreads();

            const int u  = half * 256 + tid;
            const int zb = b * NN;
            float zi = __ldcg(&g_z[zb + u]);
            float zf = __ldcg(&g_z[zb + UU + u]);
            float zo = __ldcg(&g_z[zb + 2 * UU + u]);
            float zc = __ldcg(&g_z[zb + 3 * UU + u]);

            float gi = 1.0f / (1.0f + __expf(-zi));
            float gf = 1.0f / (1.0f + __expf(-zf));
            float go = 1.0f / (1.0f + __expf(-zo));
            float ct = tanhf(zc);

            const float* mb = g_mem + b * (MM * UU) + u;
            float c0 = 0.f, c1 = 0.f, c2 = 0.f, c3 = 0.f;
#pragma unroll
            for (int s = 0; s < MM; s += 4) {
                c0 += s_ew[s + 0] * __ldcg(&mb[(s + 0) * UU]);
                c1 += s_ew[s + 1] * __ldcg(&mb[(s + 1) * UU]);
                c2 += s_ew[s + 2] * __ldcg(&mb[(s + 2) * UU]);
                c3 += s_ew[s + 3] * __ldcg(&mb[(s + 3) * UU]);
            }
            float contrib = (c0 + c1) + (c2 + c3);

            float cc = gf * contrib + gi * ct;
            float hh = go * tanhf(cc);

            g_mem[b * (MM * UU) + (t & (MM - 1)) * UU + u] = cc;
            g_h[b * UU + u] = hh;
            out[b * (TT * UU) + t * UU + u] = hh;
        }

        grid_barrier(&my_epoch);
    }
}

// =====================================================================
// Launch: 2 graph nodes. No allocations, graph-capturable.
// =====================================================================
extern "C" void kernel_launch(void* const* d_in, const int* in_sizes, int n_in,
                              void* d_out, int out_size)
{
    (void)in_sizes; (void)n_in; (void)out_size;
    const float* x  = (const float*)d_in[0];
    const float* Wi = (const float*)d_in[1];
    const float* Ui = (const float*)d_in[2];
    const float* bi = (const float*)d_in[3];
    const float* Wf = (const float*)d_in[4];
    const float* Uf = (const float*)d_in[5];
    const float* bf = (const float*)d_in[6];
    const float* Wo = (const float*)d_in[7];
    const float* Uo = (const float*)d_in[8];
    const float* bo = (const float*)d_in[9];
    const float* Wc = (const float*)d_in[10];
    const float* Uc = (const float*)d_in[11];
    const float* bc = (const float*)d_in[12];
    const float* We = (const float*)d_in[13];
    const float* Ue = (const float*)d_in[14];
    const float* be = (const float*)d_in[15];
    float* out = (float*)d_out;

    cudaFuncSetAttribute(xlstm_persistent,
                         cudaFuncAttributeMaxDynamicSharedMemorySize, SMEM_BYTES);

    init_kernel<<<1024, 256>>>(Wi, Ui, bi, Wf, Uf, bf, Wo, Uo, bo,
                               Wc, Uc, bc, We, Ue, be);
    xlstm_persistent<<<NBLK, 256, SMEM_BYTES>>>(x, out);
}

// round 5
// speedup vs baseline: 1.2028x; 1.2028x over previous
#include <cuda_runtime.h>
#include <cstdint>

// Problem constants
#define BB 64      // batch
#define TT 512     // seq len
#define DD 256     // input dim
#define UU 512     // units
#define MM 64      // memory slots
#define NN 2112    // 4*U + M
#define KK 768     // D + U

#define NBLK 132   // 66 n-stripes x 2 batch-halves

// dynamic smem layout (float offsets)
//  s_W   : [768][32]              24576 f  (persistent weight stripe)
//  s_a   : 2 x [128][34]           8704 f  (A double buffer; aliased by s_p u64[4352])
//  s_mem : [64][256]              16384 f  (block-private shift-register memory)
#define SA_STRIDE 34
#define SA_BUF 4352
#define SA_OFF 24576
#define SM_OFF 33280
#define SMEM_FLOATS 49664
#define SMEM_BYTES (SMEM_FLOATS * 4)   // 198656 B

// -------- device scratch (no allocations allowed) --------
__device__ float g_W[KK * NN];
__device__ float g_b[NN];
__device__ float g_h[BB * UU];
__device__ float g_z[BB * NN];
__device__ unsigned g_count = 0;
__device__ unsigned g_epoch = 0;

// =====================================================================
// Init: pack W/U/b into [768 x 2112], zero h.
// =====================================================================
__global__ void init_kernel(
    const float* __restrict__ Wi, const float* __restrict__ Ui, const float* __restrict__ bi,
    const float* __restrict__ Wf, const float* __restrict__ Uf, const float* __restrict__ bf,
    const float* __restrict__ Wo, const float* __restrict__ Uo, const float* __restrict__ bo,
    const float* __restrict__ Wc, const float* __restrict__ Uc, const float* __restrict__ bc,
    const float* __restrict__ We, const float* __restrict__ Ue, const float* __restrict__ be)
{
    int stride = gridDim.x * blockDim.x;
    int t0 = blockIdx.x * blockDim.x + threadIdx.x;

    for (int i = t0; i < KK * NN; i += stride) {
        int k = i / NN;
        int n = i - k * NN;
        float v;
        if (n < 4 * UU) {
            int g = n >> 9;
            int col = n & (UU - 1);
            const float* s;
            if (k < DD) {
                s = (g == 0) ? Wi : (g == 1) ? Wf : (g == 2) ? Wo : Wc;
                v = s[k * UU + col];
            } else {
                s = (g == 0) ? Ui : (g == 1) ? Uf : (g == 2) ? Uo : Uc;
                v = s[(k - DD) * UU + col];
            }
        } else {
            int col = n - 4 * UU;
            v = (k < DD) ? We[k * MM + col] : Ue[(k - DD) * MM + col];
        }
        g_W[i] = v;
    }
    for (int i = t0; i < NN; i += stride) {
        float v;
        if (i < 4 * UU) {
            int g = i >> 9;
            int col = i & (UU - 1);
            v = (g == 0) ? bi[col] : (g == 1) ? bf[col] : (g == 2) ? bo[col] : bc[col];
        } else {
            v = be[i - 4 * UU];
        }
        g_b[i] = v;
    }
    for (int i = t0; i < BB * UU; i += stride) g_h[i] = 0.0f;
}

// =====================================================================
// Grid-wide software barrier (count + monotonic epoch). 132 co-resident.
// =====================================================================
__device__ __forceinline__ void grid_barrier(unsigned* my_epoch)
{
    __syncthreads();
    if (threadIdx.x == 0) {
        unsigned target = *my_epoch + 1u;
        __threadfence();
        unsigned v = atomicAdd(&g_count, 1u);
        if (v == NBLK - 1) {
            atomicExch(&g_count, 0u);
            __threadfence();
            atomicExch(&g_epoch, target);
        } else {
            while ((int)(*((volatile unsigned*)&g_epoch) - target) < 0) { }
        }
        *my_epoch = target;
    }
    __syncthreads();
}

__device__ __forceinline__ void ffma2(unsigned long long& acc,
                                      unsigned long long a2,
                                      unsigned long long b2)
{
    asm("fma.rn.f32x2 %0, %1, %2, %0;" : "+l"(acc) : "l"(a2), "l"(b2));
}

// 16 k-steps: lane tile 4m x 8n (16 packed f32x2 accumulators).
__device__ __forceinline__ void compute_chunk(const float* __restrict__ sa,
                                              const float* __restrict__ sw,
                                              unsigned long long acc[16])
{
#pragma unroll
    for (int r = 0; r < 16; ++r) {
        float2 a01 = *(const float2*)(sa + r * SA_STRIDE);
        float2 a23 = *(const float2*)(sa + r * SA_STRIDE + 2);
        const ulonglong2* bw = (const ulonglong2*)(sw + r * 32);
        ulonglong2 bv0 = bw[0];
        ulonglong2 bv1 = bw[1];
        unsigned long long a2_0, a2_1, a2_2, a2_3;
        asm("mov.b64 %0, {%1, %1};" : "=l"(a2_0) : "f"(a01.x));
        asm("mov.b64 %0, {%1, %1};" : "=l"(a2_1) : "f"(a01.y));
        asm("mov.b64 %0, {%1, %1};" : "=l"(a2_2) : "f"(a23.x));
        asm("mov.b64 %0, {%1, %1};" : "=l"(a2_3) : "f"(a23.y));
        ffma2(acc[0],  a2_0, bv0.x); ffma2(acc[1],  a2_0, bv0.y);
        ffma2(acc[2],  a2_0, bv1.x); ffma2(acc[3],  a2_0, bv1.y);
        ffma2(acc[4],  a2_1, bv0.x); ffma2(acc[5],  a2_1, bv0.y);
        ffma2(acc[6],  a2_1, bv1.x); ffma2(acc[7],  a2_1, bv1.y);
        ffma2(acc[8],  a2_2, bv0.x); ffma2(acc[9],  a2_2, bv0.y);
        ffma2(acc[10], a2_2, bv1.x); ffma2(acc[11], a2_2, bv1.y);
        ffma2(acc[12], a2_3, bv0.x); ffma2(acc[13], a2_3, bv0.y);
        ffma2(acc[14], a2_3, bv1.x); ffma2(acc[15], a2_3, bv1.y);
    }
}

// =====================================================================
// Persistent kernel: 512 x { GEMM -> barrier -> pointwise -> barrier }.
// Block = (n-stripe, batch-half): z[m0:m0+32, n0:n0+32] over K=768.
// 8 warps split K (96 each, staged 16 at a time, double-buffered).
// =====================================================================
__global__ __launch_bounds__(256, 1) void xlstm_persistent(
    const float* __restrict__ x, float* __restrict__ out)
{
    extern __shared__ float smem[];
    float* s_W  = smem;
    float* s_aF = smem + SA_OFF;
    unsigned long long* s_p = (unsigned long long*)(smem + SA_OFF); // alias
    float* s_mem = smem + SM_OFF;
    __shared__ float s_e[MM];
    __shared__ float s_ew[MM];

    const int tid   = threadIdx.x;
    const int lane  = tid & 31;
    const int warp  = tid >> 5;           // k-group 0..7
    const int blk   = blockIdx.x;
    const int n0    = (blk >> 1) * 32;
    const int m0    = (blk & 1) * 32;
    const int mq    = lane >> 2;          // 0..7  (m-subgroup)
    const int nq    = lane & 3;           // 0..3  (n-subgroup)
    const int qk    = nq * 4;             // k offset of this lane's float4
    const int kwarp = warp * 96;

    // ---- load W stripe into smem once (persistent across all 512 steps)
#pragma unroll 4
    for (int q = 0; q < 96; ++q) {
        int i = tid + q * 256;            // 0..24575
        int k = i >> 5, n = i & 31;
        s_W[i] = g_W[k * NN + n0 + n];
    }
    // ---- zero block-private memory
    for (int i = tid; i < MM * 256; i += 256) s_mem[i] = 0.0f;

    unsigned my_epoch = 0;
    if (tid == 0) my_epoch = *((volatile unsigned*)&g_epoch);
    __syncthreads();

#define LOAD_CHUNK(cc)                                                        \
    {                                                                         \
        int kb = kwarp + (cc) * 16 + qk;                                      \
        if (kb < DD) {                                                        \
            const float* bp = x + (size_t)(m0 + mq) * (TT * DD)               \
                                + (size_t)t * DD + kb;                        \
            v0 = *(const float4*)(bp);                                        \
            v1 = *(const float4*)(bp + (size_t)8  * (TT * DD));               \
            v2 = *(const float4*)(bp + (size_t)16 * (TT * DD));               \
            v3 = *(const float4*)(bp + (size_t)24 * (TT * DD));               \
        } else {                                                              \
            const float* hp = g_h + (m0 + mq) * UU + (kb - DD);               \
            v0 = __ldcg((const float4*)(hp));                                 \
            v1 = __ldcg((const float4*)(hp + 8  * UU));                       \
            v2 = __ldcg((const float4*)(hp + 16 * UU));                       \
            v3 = __ldcg((const float4*)(hp + 24 * UU));                       \
        }                                                                     \
    }

#define STORE_CHUNK(bsel)                                                     \
    {                                                                         \
        float* d = s_aF + (bsel) * SA_BUF                                     \
                 + (warp * 16 + qk) * SA_STRIDE + mq;                         \
        d[0 * SA_STRIDE + 0]  = v0.x; d[1 * SA_STRIDE + 0]  = v0.y;           \
        d[2 * SA_STRIDE + 0]  = v0.z; d[3 * SA_STRIDE + 0]  = v0.w;           \
        d[0 * SA_STRIDE + 8]  = v1.x; d[1 * SA_STRIDE + 8]  = v1.y;           \
        d[2 * SA_STRIDE + 8]  = v1.z; d[3 * SA_STRIDE + 8]  = v1.w;           \
        d[0 * SA_STRIDE + 16] = v2.x; d[1 * SA_STRIDE + 16] = v2.y;           \
        d[2 * SA_STRIDE + 16] = v2.z; d[3 * SA_STRIDE + 16] = v2.w;           \
        d[0 * SA_STRIDE + 24] = v3.x; d[1 * SA_STRIDE + 24] = v3.y;           \
        d[2 * SA_STRIDE + 24] = v3.z; d[3 * SA_STRIDE + 24] = v3.w;           \
    }

    for (int t = 0; t < TT; ++t) {
        // ============================ GEMM ============================
        unsigned long long acc[16];
#pragma unroll
        for (int q = 0; q < 16; ++q) acc[q] = 0ull;

        float4 v0, v1, v2, v3;
        LOAD_CHUNK(0)
        STORE_CHUNK(0)
        __syncthreads();

#pragma unroll 1
        for (int c = 0; c < 6; ++c) {
            const int cur = c & 1;
            if (c < 5) LOAD_CHUNK(c + 1)
            compute_chunk(s_aF + cur * SA_BUF + (warp * 16) * SA_STRIDE + 4 * mq,
                          s_W + (kwarp + c * 16) * 32 + 8 * nq, acc);
            if (c < 5) STORE_CHUNK(1 - cur)
            __syncthreads();
        }

        // deterministic cross-kgroup reduction (s_p aliases A buffers)
        {
            unsigned long long* pp = s_p + ((size_t)warp * 32 + 4 * mq) * 17 + 4 * nq;
#pragma unroll
            for (int mi = 0; mi < 4; ++mi)
#pragma unroll
                for (int p = 0; p < 4; ++p)
                    pp[mi * 17 + p] = acc[mi * 4 + p];
        }
        __syncthreads();
#pragma unroll
        for (int q = 0; q < 2; ++q) {
            int o  = tid + q * 256;          // 0..511
            int m  = o >> 4;                  // 0..31
            int np = o & 15;
            float2 s = *(const float2*)(g_b + n0 + 2 * np);
#pragma unroll
            for (int kg = 0; kg < 8; ++kg) {
                unsigned long long u = s_p[((size_t)kg * 32 + m) * 17 + np];
                float lo, hi;
                asm("mov.b64 {%0, %1}, %2;" : "=f"(lo), "=f"(hi) : "l"(u));
                s.x += lo; s.y += hi;
            }
            *(float2*)(g_z + (size_t)(m0 + m) * NN + n0 + 2 * np) = s;
        }

        grid_barrier(&my_epoch);

        // ========================== pointwise =========================
        if (blk < 2 * BB) {
            const int b    = blk >> 1;
            const int half = blk & 1;

            if (tid < 32) {
                float z0 = __ldcg(&g_z[b * NN + 4 * UU + tid]);
                float z1 = __ldcg(&g_z[b * NN + 4 * UU + 32 + tid]);
                float mx = fmaxf(z0, z1);
#pragma unroll
                for (int o = 16; o > 0; o >>= 1)
                    mx = fmaxf(mx, __shfl_xor_sync(0xffffffffu, mx, o));
                float e0 = __expf(z0 - mx);
                float e1 = __expf(z1 - mx);
                float sm = e0 + e1;
#pragma unroll
                for (int o = 16; o > 0; o >>= 1)
                    sm += __shfl_xor_sync(0xffffffffu, sm, o);
                float inv = 1.0f / sm;
                s_e[tid]      = e0 * inv;
                s_e[tid + 32] = e1 * inv;
            }
            __syncthreads();
            // physical slot s holds c from step t'=s mod 64; age m = t-1-t'
            if (tid < MM) s_ew[tid] = s_e[(t - 1 - tid) & (MM - 1)];
            __syncthreads();

            const int u  = half * 256 + tid;
            const int zb = b * NN;
            float zi = __ldcg(&g_z[zb + u]);
            float zf = __ldcg(&g_z[zb + UU + u]);
            float zo = __ldcg(&g_z[zb + 2 * UU + u]);
            float zc = __ldcg(&g_z[zb + 3 * UU + u]);

            float gi = 1.0f / (1.0f + __expf(-zi));
            float gf = 1.0f / (1.0f + __expf(-zf));
            float go = 1.0f / (1.0f + __expf(-zo));
            float ct = tanhf(zc);

            const float* mb = s_mem + tid;
            float c0 = 0.f, c1 = 0.f, c2 = 0.f, c3 = 0.f;
#pragma unroll
            for (int s = 0; s < MM; s += 4) {
                c0 += s_ew[s + 0] * mb[(s + 0) * 256];
                c1 += s_ew[s + 1] * mb[(s + 1) * 256];
                c2 += s_ew[s + 2] * mb[(s + 2) * 256];
                c3 += s_ew[s + 3] * mb[(s + 3) * 256];
            }
            float contrib = (c0 + c1) + (c2 + c3);

            float cc = gf * contrib + gi * ct;
            float hh = go * tanhf(cc);

            s_mem[(t & (MM - 1)) * 256 + tid] = cc;   // overwrite oldest slot
            g_h[b * UU + u] = hh;
            out[(size_t)b * (TT * UU) + (size_t)t * UU + u] = hh;
        }

        grid_barrier(&my_epoch);
    }
#undef LOAD_CHUNK
#undef STORE_CHUNK
}

// =====================================================================
// Launch: 2 graph nodes. No allocations, graph-capturable.
// =====================================================================
extern "C" void kernel_launch(void* const* d_in, const int* in_sizes, int n_in,
                              void* d_out, int out_size)
{
    (void)in_sizes; (void)n_in; (void)out_size;
    const float* x  = (const float*)d_in[0];
    const float* Wi = (const float*)d_in[1];
    const float* Ui = (const float*)d_in[2];
    const float* bi = (const float*)d_in[3];
    const float* Wf = (const float*)d_in[4];
    const float* Uf = (const float*)d_in[5];
    const float* bf = (const float*)d_in[6];
    const float* Wo = (const float*)d_in[7];
    const float* Uo = (const float*)d_in[8];
    const float* bo = (const float*)d_in[9];
    const float* Wc = (const float*)d_in[10];
    const float* Uc = (const float*)d_in[11];
    const float* bc = (const float*)d_in[12];
    const float* We = (const float*)d_in[13];
    const float* Ue = (const float*)d_in[14];
    const float* be = (const float*)d_in[15];
    float* out = (float*)d_out;

    cudaFuncSetAttribute(xlstm_persistent,
                         cudaFuncAttributeMaxDynamicSharedMemorySize, SMEM_BYTES);

    init_kernel<<<1024, 256>>>(Wi, Ui, bi, Wf, Uf, bf, Wo, Uo, bo,
                               Wc, Uc, bc, We, Ue, be);
    xlstm_persistent<<<NBLK, 256, SMEM_BYTES>>>(x, out);
}